// round 14
// baseline (speedup 1.0000x reference)
#include <cuda_runtime.h>

// FeedForwardAttention — algebraically reduced, single persistent kernel.
//   attns[b,q,:] = softmax_k(u . key[b,k]),  u = Wk^T fck_w
//   out[b,q,:]   = Wv @ (sum_k e_k value[b,k,:]) / (sum_k e_k) + bv  (q-independent)
// R7 skeleton; P1 doubles in-flight bytes/warp: K = 2-row register-batched LDG,
// V = cp.async into warp-private smem (no register cost). P4 = cached-row stcs.

#define BB 8
#define LL 2048
#define CC 1024
#define GRID 148
#define TPB 512
#define P0B 128
#define P1B 128
// dynamic smem: su4 4KB | staging 16 warps x 8KB (unioned with sbuf 32KB) | sew
#define SM_SU    0
#define SM_STAGE 4096
#define SM_SEW   (4096 + 131072)
#define SMEM_TOTAL (4096 + 131072 + 256)

__device__ float g_upart[P0B * CC];
__device__ float g_u[CC];
__device__ float g_vpart[P1B * CC];
__device__ float g_eblk[P1B];
__device__ float g_vbar[BB * CC];
__device__ float g_outs[BB * CC];
__device__ unsigned g_count = 0;
__device__ unsigned g_gen = 0;

__device__ __forceinline__ void grid_barrier() {
    __syncthreads();
    if (threadIdx.x == 0) {
        unsigned gen = *(volatile unsigned*)&g_gen;
        __threadfence();
        if (atomicAdd(&g_count, 1u) == GRID - 1) {
            atomicExch(&g_count, 0u);
            __threadfence();
            atomicAdd(&g_gen, 1u);
        } else {
            while (*(volatile unsigned*)&g_gen == gen) { }
            __threadfence();
        }
    }
    __syncthreads();
}

__device__ __forceinline__ unsigned smem_u32(const void* p) {
    unsigned a;
    asm("{ .reg .u64 tmp; cvta.to.shared.u64 tmp, %1; cvt.u32.u64 %0, tmp; }"
        : "=r"(a) : "l"(p));
    return a;
}

__global__ void __launch_bounds__(TPB, 1) k_fused(
    const float* __restrict__ key, const float* __restrict__ value,
    const float* __restrict__ Wk, const float* __restrict__ Wv,
    const float* __restrict__ bv, const float* __restrict__ fckw,
    float4* __restrict__ out)
{
    extern __shared__ char pool[];
    float4* su4 = (float4*)(pool + SM_SU);               // 4KB staged u
    float4 (*sbuf)[CC / 4] = (float4(*)[CC / 4])(pool + SM_STAGE); // post-loop
    float* sew = (float*)(pool + SM_SEW);
    float* s_scale = (float*)(pool + SM_SEW + 64);

    const int bk = blockIdx.x, t = threadIdx.x;
    const int w = t >> 5, lane = t & 31;

    // ---- P0: u partials (128 blocks x 8 o-rows; thread covers 2 cols) -----
    if (bk < P0B) {
        int o0 = bk * 8;
        float a0 = 0.f, a1 = 0.f;
#pragma unroll
        for (int o = 0; o < 8; ++o) {
            float f = fckw[o0 + o];
            const float* wr = Wk + (size_t)(o0 + o) * CC;
            a0 += f * wr[t];
            a1 += f * wr[t + 512];
        }
        g_upart[bk * CC + t]       = a0;
        g_upart[bk * CC + t + 512] = a1;
    }
    grid_barrier();

    // ---- P0b: u reduce (8 blocks x 128 columns) ---------------------------
    if (bk < 8 && t < 128) {
        int c = bk * 128 + t;
        float acc = 0.f;
#pragma unroll
        for (int j = 0; j < P0B; ++j) acc += g_upart[j * CC + c];
        g_u[c] = acc;
    }
    grid_barrier();

    // ---- P1: fused (128 blocks x 128 rows). K in regs, V via cp.async -----
    if (bk < P1B) {
        if (t < 256) su4[t] = ((const float4*)g_u)[t];
        __syncthreads();
        const int b = bk >> 4;
        const int row0 = b * LL + (bk & 15) * 128;
        // warp-private staging: rowA at +0 (4KB), rowB at +4096
        const unsigned stA = smem_u32(pool + SM_STAGE) + (unsigned)w * 8192u;
        const unsigned stB = stA + 4096u;

        float4 acc[8];
#pragma unroll
        for (int i = 0; i < 8; ++i) acc[i] = make_float4(0.f, 0.f, 0.f, 0.f);
        float e_acc = 0.f;

#pragma unroll
        for (int p = 0; p < 4; ++p) {
            const int rA = row0 + p * 32 + w;
            const int rB = rA + 16;
            // 1) issue V for both rows into smem (no register cost)
            {
                const char* vA = (const char*)(value + (size_t)rA * CC) + lane * 16;
                const char* vB = (const char*)(value + (size_t)rB * CC) + lane * 16;
                const unsigned dA = stA + lane * 16u;
                const unsigned dB = stB + lane * 16u;
#pragma unroll
                for (int i = 0; i < 8; ++i)
                    asm volatile("cp.async.cg.shared.global [%0], [%1], 16;"
                                 :: "r"(dA + i * 512u), "l"(vA + i * 512) : "memory");
#pragma unroll
                for (int i = 0; i < 8; ++i)
                    asm volatile("cp.async.cg.shared.global [%0], [%1], 16;"
                                 :: "r"(dB + i * 512u), "l"(vB + i * 512) : "memory");
                asm volatile("cp.async.commit_group;" ::: "memory");
            }
            // 2) K: 2 rows register-batched
            const float4* kA = (const float4*)key + (size_t)rA * 256;
            const float4* kB = (const float4*)key + (size_t)rB * 256;
            float4 ka[8], kb[8];
#pragma unroll
            for (int i = 0; i < 8; ++i) ka[i] = kA[lane + i * 32];
#pragma unroll
            for (int i = 0; i < 8; ++i) kb[i] = kB[lane + i * 32];
            // 3) dots
            float d0 = 0.f, d1 = 0.f;
#pragma unroll
            for (int i = 0; i < 8; ++i) {
                float4 uv = su4[lane + i * 32];
                d0 += ka[i].x * uv.x + ka[i].y * uv.y + ka[i].z * uv.z + ka[i].w * uv.w;
                d1 += kb[i].x * uv.x + kb[i].y * uv.y + kb[i].z * uv.z + kb[i].w * uv.w;
            }
#pragma unroll
            for (int o = 16; o; o >>= 1) {
                d0 += __shfl_xor_sync(0xFFFFFFFFu, d0, o);
                d1 += __shfl_xor_sync(0xFFFFFFFFu, d1, o);
            }
            const float e0 = __expf(d0), e1 = __expf(d1);
            e_acc += e0 + e1;
            // 4) consume V from smem
            asm volatile("cp.async.wait_group 0;" ::: "memory");
            __syncwarp();
#pragma unroll
            for (int i = 0; i < 8; ++i) {
                float4 va, vb2;
                asm volatile("ld.shared.v4.f32 {%0,%1,%2,%3}, [%4];"
                             : "=f"(va.x), "=f"(va.y), "=f"(va.z), "=f"(va.w)
                             : "r"(stA + lane * 16u + i * 512u));
                asm volatile("ld.shared.v4.f32 {%0,%1,%2,%3}, [%4];"
                             : "=f"(vb2.x), "=f"(vb2.y), "=f"(vb2.z), "=f"(vb2.w)
                             : "r"(stB + lane * 16u + i * 512u));
                acc[i].x += e0 * va.x + e1 * vb2.x;
                acc[i].y += e0 * va.y + e1 * vb2.y;
                acc[i].z += e0 * va.z + e1 * vb2.z;
                acc[i].w += e0 * va.w + e1 * vb2.w;
            }
            __syncwarp();   // staging reuse next iteration
        }

        // all staging dead; reuse region as sbuf. Sync BEFORE writes.
        __syncthreads();
        if (w < 8) {
#pragma unroll
            for (int i = 0; i < 8; ++i) sbuf[w][lane + i * 32] = acc[i];
        }
        if (lane == 0) sew[w] = e_acc;
        __syncthreads();
        if (w >= 8) {
            int bf = w - 8;
#pragma unroll
            for (int i = 0; i < 8; ++i) {
                float4 c = sbuf[bf][lane + i * 32];
                c.x += acc[i].x; c.y += acc[i].y; c.z += acc[i].z; c.w += acc[i].w;
                sbuf[bf][lane + i * 32] = c;
            }
        }
        __syncthreads();
        if (t < 256) {
            float4 s = make_float4(0.f, 0.f, 0.f, 0.f);
#pragma unroll
            for (int j = 0; j < 8; ++j) {
                float4 c = sbuf[j][t];
                s.x += c.x; s.y += c.y; s.z += c.z; s.w += c.w;
            }
            ((float4*)g_vpart)[bk * 256 + t] = s;
        } else if (w == 8) {
            float s = (lane < 16) ? sew[lane] : 0.f;
#pragma unroll
            for (int o = 16; o; o >>= 1) s += __shfl_xor_sync(0xFFFFFFFFu, s, o);
            if (lane == 0) g_eblk[bk] = s;
        }
    }
    grid_barrier();

    // ---- P2: vbar[b][c] = sum_j vpart / esum[b]  (8 blocks) ---------------
    if (bk < BB) {
        if (t == 0) {
            float es = 0.f;
#pragma unroll
            for (int j = 0; j < 16; ++j) es += g_eblk[bk * 16 + j];
            *s_scale = 1.f / es;
        }
        float a0 = 0.f, a1 = 0.f;
#pragma unroll
        for (int j = 0; j < 16; ++j) {
            const float* vp = g_vpart + (size_t)(bk * 16 + j) * CC;
            a0 += vp[t];
            a1 += vp[t + 512];
        }
        __syncthreads();
        g_vbar[bk * CC + t]       = a0 * (*s_scale);
        g_vbar[bk * CC + t + 512] = a1 * (*s_scale);
    }
    grid_barrier();

    // ---- P3: outs[b][d] = Wv[d] . vbar[b] + bv[d]  (64 blocks x 16 d) -----
    if (bk < 64) {
        int d = bk * 16 + w;
        const float4* wp = (const float4*)(Wv + (size_t)d * CC);
        const float4* vb = (const float4*)g_vbar;
        float acc[BB];
#pragma unroll
        for (int b = 0; b < BB; ++b) acc[b] = 0.f;
#pragma unroll
        for (int i = 0; i < 8; ++i) {
            int idx = lane + i * 32;
            float4 wv = wp[idx];
#pragma unroll
            for (int b = 0; b < BB; ++b) {
                float4 v = vb[b * 256 + idx];
                acc[b] += wv.x * v.x + wv.y * v.y + wv.z * v.z + wv.w * v.w;
            }
        }
#pragma unroll
        for (int b = 0; b < BB; ++b)
#pragma unroll
            for (int o = 16; o; o >>= 1)
                acc[b] += __shfl_xor_sync(0xFFFFFFFFu, acc[b], o);
        if (lane == 0) {
            float bias = bv[d];
#pragma unroll
            for (int b = 0; b < BB; ++b) g_outs[b * CC + d] = acc[b] + bias;
        }
    }
    grid_barrier();

    // ---- P4: broadcast outs[b,:] (64MB streaming write, cached rows) ------
    {
        const int i0 = bk * TPB + t;
        const int d4 = i0 & 255;        // fixed: stride 148*512 ≡ 0 mod 256
        const float4* os = (const float4*)g_outs;
        float4 r0 = os[0 * 256 + d4], r1 = os[1 * 256 + d4];
        float4 r2 = os[2 * 256 + d4], r3 = os[3 * 256 + d4];
        float4 r4 = os[4 * 256 + d4], r5 = os[5 * 256 + d4];
        float4 r6 = os[6 * 256 + d4], r7 = os[7 * 256 + d4];
        const int total4 = BB * LL * CC / 4;
        for (int i = i0; i < total4; i += GRID * TPB) {
            int b = i >> 19;
            float4 r = (b < 4) ? ((b < 2) ? (b == 0 ? r0 : r1) : (b == 2 ? r2 : r3))
                               : ((b < 6) ? (b == 4 ? r4 : r5) : (b == 6 ? r6 : r7));
            __stcs(out + i, r);
        }
    }
}

extern "C" void kernel_launch(void* const* d_in, const int* in_sizes, int n_in,
                              void* d_out, int out_size) {
    const float* key   = (const float*)d_in[1];
    const float* value = (const float*)d_in[2];
    const float* Wk    = (const float*)d_in[5];
    const float* Wv    = (const float*)d_in[7];
    const float* bv    = (const float*)d_in[8];
    const float* fckw  = (const float*)d_in[11];
    // Idempotent; takes effect on the pre-capture correctness call and
    // persists on the function, so a failure under capture is harmless.
    cudaFuncSetAttribute(k_fused, cudaFuncAttributeMaxDynamicSharedMemorySize,
                         SMEM_TOTAL);
    k_fused<<<GRID, TPB, SMEM_TOTAL>>>(key, value, Wk, Wv, bv, fckw,
                                       (float4*)d_out);
}